// round 7
// baseline (speedup 1.0000x reference)
#include <cuda_runtime.h>
#include <cuda_fp16.h>

#define B_   4
#define CIN  256
#define CO_  64
#define N_   576   // 24*24
#define CV_  256

// Scratch (device globals — no allocation allowed)
__device__ unsigned g_kph[B_ * N_ * 32];   // (B, Nk, 32) half2 pairs over c
__device__ unsigned g_qph[B_ * N_ * 32];   // (B, Nq, 32)

// ---------- packed helpers ----------
__device__ __forceinline__ unsigned long long pack2(float lo, float hi) {
    unsigned long long r;
    asm("mov.b64 %0, {%1, %2};" : "=l"(r) : "f"(lo), "f"(hi));
    return r;
}
__device__ __forceinline__ void unpack2(unsigned long long v, float& lo, float& hi) {
    asm("mov.b64 {%0, %1}, %2;" : "=f"(lo), "=f"(hi) : "l"(v));
}
__device__ __forceinline__ unsigned long long ffma2(unsigned long long a,
                                                    unsigned long long b,
                                                    unsigned long long c) {
    unsigned long long d;
    asm("fma.rn.f32x2 %0, %1, %2, %3;" : "=l"(d) : "l"(a), "l"(b), "l"(c));
    return d;
}
__device__ __forceinline__ float tanhfast(float x) {
    float y;
    asm("tanh.approx.f32 %0, %1;" : "=f"(y) : "f"(x));
    return y;
}
__device__ __forceinline__ unsigned tanh_h2(unsigned x) {
    unsigned y;
    asm("tanh.approx.f16x2 %0, %1;" : "=r"(y) : "r"(x));
    return y;
}
__device__ __forceinline__ __half2 u2h(unsigned u) { return *(__half2*)&u; }
__device__ __forceinline__ unsigned h2u(__half2 h) { return *(unsigned*)&h; }

// ============================================================================
// Kernel 0: zero-init d_out (it's poisoned; we accumulate atomically into it)
// ============================================================================
__global__ void __launch_bounds__(256) zero_kernel(float4* __restrict__ o)
{
    o[blockIdx.x * 256 + threadIdx.x] = make_float4(0.f, 0.f, 0.f, 0.f);
}

// ============================================================================
// Kernel A: projections -> half2. grid (18 n-tiles of 32, B, 2), 512 thr.
// Full-K staging, ONE barrier; compute uses explicit batch-8 prefetch so the
// LDS latency is front-loaded (MLP ~16) instead of a serialized chain.
// ============================================================================
#define PROJ_SMEM_BYTES ((256 * 32 + 256 * 66) * 4)

__global__ void __launch_bounds__(512) proj_kernel(
    const float* __restrict__ key, const float* __restrict__ query,
    const float* __restrict__ Wk,  const float* __restrict__ bk,
    const float* __restrict__ Wq,  const float* __restrict__ bq)
{
    extern __shared__ float smem[];
    float (*sX)[32] = (float (*)[32])smem;               // [256 ch][32 n]
    float (*sW)[66] = (float (*)[66])(smem + 256 * 32);  // [256 ch][64 c]

    const int kind = blockIdx.z;
    const float* X    = kind ? query : key;    // (B, CIN, N)
    const float* W    = kind ? Wq    : Wk;     // (CO, CIN)
    const float* bias = kind ? bq    : bk;
    unsigned* outp    = kind ? g_qph : g_kph;  // (B, N, 32) half2

    const int b  = blockIdx.y;
    const int n0 = blockIdx.x * 32;
    const int t  = threadIdx.x;

    // stage X: 256ch x 32n as float4 (coalesced)
    {
        const int n4  = (t & 7) * 4;
        const int chb = t >> 3;                  // 0..63
        #pragma unroll
        for (int i = 0; i < 4; i++) {
            const int ch = chb + i * 64;
            *(float4*)&sX[ch][n4] =
                *(const float4*)&X[((size_t)(b * CIN + ch)) * N_ + n0 + n4];
        }
    }
    // stage W transposed: sW[ch][c] (coalesced LDG over ch)
    {
        const int ch = t & 255;
        const int cb = (t >> 8) * 32;            // 0 or 32
        #pragma unroll 8
        for (int j = 0; j < 32; j++) {
            const int cr = cb + j;
            sW[ch][cr] = W[cr * CIN + ch];
        }
    }
    __syncthreads();

    const int ng = t & 15;           // n = 2*ng, 2*ng+1
    const int c  = (t >> 4) * 2;     // c, c+1

    unsigned long long a0 = 0ull, a1 = 0ull;

    for (int ch0 = 0; ch0 < CIN; ch0 += 8) {
        unsigned long long xps[8];
        float2 ws[8];
        #pragma unroll
        for (int i = 0; i < 8; i++) {
            xps[i] = *(const unsigned long long*)&sX[ch0 + i][ng * 2];
            ws[i]  = *(const float2*)&sW[ch0 + i][c];
        }
        #pragma unroll
        for (int i = 0; i < 8; i++) {
            a0 = ffma2(xps[i], pack2(ws[i].x, ws[i].x), a0);
            a1 = ffma2(xps[i], pack2(ws[i].y, ws[i].y), a1);
        }
    }

    const float bv0 = bias[c];
    const float bv1 = bias[c + 1];
    float c0n0, c0n1, c1n0, c1n1;
    unpack2(a0, c0n0, c0n1);
    unpack2(a1, c1n0, c1n1);

    const int n  = n0 + ng * 2;
    const int cc = c >> 1;
    outp[((size_t)b * N_ + n + 0) * 32 + cc] =
        h2u(__floats2half2_rn(c0n0 + bv0, c1n0 + bv1));
    outp[((size_t)b * N_ + n + 1) * 32 + cc] =
        h2u(__floats2half2_rn(c0n1 + bv0, c1n1 + bv1));
}

// ============================================================================
// Kernel B (FUSED): per block (64q x 64k x b): compute attn tile, immediately
// contract with V into per-thread (16c x 4q) fp32x2 accumulators, atomicAdd
// the k-partial into out. MUFU (attn) and FMA (out) phases overlap across
// the 2 resident blocks per SM.
// ============================================================================
// dynamic smem layout (units: 4B words)
#define FS_SQH   0                       // uint [64][34]
#define FS_SKH   (FS_SQH + 64 * 34)      // uint [64][34]
#define FS_SWH   (FS_SKH + 64 * 34)      // uint [64] (32 used)
#define FS_SA    (FS_SWH + 64)           // float[32][68]
#define FS_SV    (FS_SA + 32 * 68)       // float[32][272]
#define FUSED_SMEM_BYTES ((FS_SV + 32 * 272) * 4)

__global__ void __launch_bounds__(256) fused_kernel(
    const float* __restrict__ value, const float* __restrict__ wf,
    const float* __restrict__ bfp, float* __restrict__ out)
{
    extern __shared__ unsigned sm[];
    unsigned (*sqh)[34] = (unsigned (*)[34])(sm + FS_SQH);
    unsigned (*skh)[34] = (unsigned (*)[34])(sm + FS_SKH);
    unsigned* swh       = sm + FS_SWH;
    float (*sA)[68]     = (float (*)[68])(sm + FS_SA);
    float (*sV)[272]    = (float (*)[272])(sm + FS_SV);

    const int b  = blockIdx.z;
    const int q0 = blockIdx.x * 64;
    const int k0 = blockIdx.y * 64;
    const int t  = threadIdx.x;

    // ---- stage q/k half2 tiles (64 rows x 32 half2 each) ----
    #pragma unroll
    for (int j = 0; j < 4; j++) {
        const int idx = t + j * 256;       // 1024 uint2 per tile
        const int r = idx >> 4;            // 0..63
        const int u = (idx & 15) * 2;
        *(uint2*)&sqh[r][u] = *(const uint2*)&g_qph[((size_t)b * N_ + q0 + r) * 32 + u];
        *(uint2*)&skh[r][u] = *(const uint2*)&g_kph[((size_t)b * N_ + k0 + r) * 32 + u];
    }
    if (t < 32) {
        const float2 w = *(const float2*)&wf[t * 2];
        swh[t] = h2u(__floats2half2_rn(w.x, w.y));
    }
    const float bf = __ldg(bfp);
    __syncthreads();

    // out accumulators: thread = 16c x 4q
    const int q4 = (t & 15) * 4;          // q offset in tile
    const int cb = (t >> 4) * 16;         // c base
    unsigned long long acc[16][2];
    #pragma unroll
    for (int i = 0; i < 16; i++) { acc[i][0] = 0ull; acc[i][1] = 0ull; }

    // attn-phase mapping: q = t&63 (2 warps span 64 q), 8 k per thread
    const int qa    = t & 63;
    const int kbase = (t >> 6) * 8;       // warp-pair constant
    const unsigned* __restrict__ qrow = sqh[qa];

    #pragma unroll
    for (int ck = 0; ck < 2; ck++) {
        const int kc = ck * 32;

        // ---- attn: 32k x 64q tile -> sA ----
        __half2 ae[8], ao[8];
        #pragma unroll
        for (int i = 0; i < 8; i++) { ae[i] = __float2half2_rn(0.f); ao[i] = ae[i]; }

        #pragma unroll 4
        for (int cc = 0; cc < 32; cc += 2) {
            const uint2 qv = *(const uint2*)&qrow[cc];
            const uint2 wv = *(const uint2*)&swh[cc];
            #pragma unroll
            for (int i = 0; i < 8; i++) {
                const uint2 kv = *(const uint2*)&skh[kc + kbase + i][cc];
                const unsigned t0 = tanh_h2(h2u(__hadd2(u2h(kv.x), u2h(qv.x))));
                const unsigned t1 = tanh_h2(h2u(__hadd2(u2h(kv.y), u2h(qv.y))));
                ae[i] = __hfma2(u2h(t0), u2h(wv.x), ae[i]);
                ao[i] = __hfma2(u2h(t1), u2h(wv.y), ao[i]);
            }
        }
        #pragma unroll
        for (int i = 0; i < 8; i++) {
            const float2 fe = __half22float2(ae[i]);
            const float2 fo = __half22float2(ao[i]);
            const float s = bf + ((fe.x + fe.y) + (fo.x + fo.y));
            sA[kbase + i][qa] = fmaf(0.5f, tanhfast(0.5f * s), 0.5f);  // sigmoid
        }

        // ---- stage V chunk: sV[kk][c], kk in [0,32), c in [0,256) ----
        {
            const int kk  = t & 31;
            const int cb2 = t >> 5;                // 0..7
            const int kg  = k0 + kc + kk;
            #pragma unroll 8
            for (int j = 0; j < 32; j++) {
                const int c = cb2 + j * 8;
                sV[kk][c] = value[((size_t)(b * CV_ + c)) * N_ + kg];
            }
        }
        __syncthreads();

        // ---- out accumulate: acc[c][q-pair] += V[c,kk] * A[kk,q] ----
        #pragma unroll 4
        for (int kk = 0; kk < 32; kk++) {
            const ulonglong2 a2 = *(const ulonglong2*)&sA[kk][q4];   // 4 q
            #pragma unroll
            for (int j = 0; j < 4; j++) {
                const float4 v4 = *(const float4*)&sV[kk][cb + j * 4];
                const unsigned long long v0 = pack2(v4.x, v4.x);
                const unsigned long long v1 = pack2(v4.y, v4.y);
                const unsigned long long v2 = pack2(v4.z, v4.z);
                const unsigned long long v3 = pack2(v4.w, v4.w);
                acc[j * 4 + 0][0] = ffma2(v0, a2.x, acc[j * 4 + 0][0]);
                acc[j * 4 + 0][1] = ffma2(v0, a2.y, acc[j * 4 + 0][1]);
                acc[j * 4 + 1][0] = ffma2(v1, a2.x, acc[j * 4 + 1][0]);
                acc[j * 4 + 1][1] = ffma2(v1, a2.y, acc[j * 4 + 1][1]);
                acc[j * 4 + 2][0] = ffma2(v2, a2.x, acc[j * 4 + 2][0]);
                acc[j * 4 + 2][1] = ffma2(v2, a2.y, acc[j * 4 + 2][1]);
                acc[j * 4 + 3][0] = ffma2(v3, a2.x, acc[j * 4 + 3][0]);
                acc[j * 4 + 3][1] = ffma2(v3, a2.y, acc[j * 4 + 3][1]);
            }
        }
        __syncthreads();   // protect sA/sV before next chunk overwrites
    }

    // ---- atomically add k-partial into out ----
    #pragma unroll
    for (int i = 0; i < 16; i++) {
        const int c = cb + i;
        float o0, o1, o2, o3;
        unpack2(acc[i][0], o0, o1);
        unpack2(acc[i][1], o2, o3);
        float* op = out + ((size_t)(b * CV_ + c)) * N_ + q0 + q4;
        atomicAdd(op + 0, o0);
        atomicAdd(op + 1, o1);
        atomicAdd(op + 2, o2);
        atomicAdd(op + 3, o3);
    }
}

// ============================================================================
extern "C" void kernel_launch(void* const* d_in, const int* in_sizes, int n_in,
                              void* d_out, int out_size)
{
    const float* key   = (const float*)d_in[0];
    const float* query = (const float*)d_in[1];
    const float* value = (const float*)d_in[2];
    const float* Wk    = (const float*)d_in[3];
    const float* bk    = (const float*)d_in[4];
    const float* Wq    = (const float*)d_in[5];
    const float* bq    = (const float*)d_in[6];
    const float* wf    = (const float*)d_in[7];
    const float* bf    = (const float*)d_in[8];
    float* out = (float*)d_out;

    static int attr_set = 0;
    if (!attr_set) {
        cudaFuncSetAttribute(proj_kernel,
                             cudaFuncAttributeMaxDynamicSharedMemorySize,
                             PROJ_SMEM_BYTES);
        cudaFuncSetAttribute(fused_kernel,
                             cudaFuncAttributeMaxDynamicSharedMemorySize,
                             FUSED_SMEM_BYTES);
        attr_set = 1;
    }

    zero_kernel<<<(B_ * CV_ * N_) / 1024, 256>>>((float4*)out);
    proj_kernel<<<dim3(N_ / 32, B_, 2), 512, PROJ_SMEM_BYTES>>>(key, query, Wk, bk, Wq, bq);
    fused_kernel<<<dim3(N_ / 64, N_ / 64, B_), 256, FUSED_SMEM_BYTES>>>(value, wf, bf, out);
}

// round 8
// speedup vs baseline: 1.0535x; 1.0535x over previous
#include <cuda_runtime.h>
#include <cuda_fp16.h>

#define B_     4
#define CIN    256
#define CO_    64
#define N_     576   // 24*24
#define CV_    256
#define NCHUNK 18    // 576 / 32

// Scratch (device globals — no allocation allowed)
__device__ unsigned g_kph[B_ * N_ * 32];   // (B, Nk, 32) half2 pairs over c
__device__ unsigned g_qph[B_ * N_ * 32];   // (B, Nq, 32)

// ---------- packed helpers ----------
__device__ __forceinline__ unsigned long long pack2(float lo, float hi) {
    unsigned long long r;
    asm("mov.b64 %0, {%1, %2};" : "=l"(r) : "f"(lo), "f"(hi));
    return r;
}
__device__ __forceinline__ void unpack2(unsigned long long v, float& lo, float& hi) {
    asm("mov.b64 {%0, %1}, %2;" : "=f"(lo), "=f"(hi) : "l"(v));
}
__device__ __forceinline__ unsigned long long ffma2(unsigned long long a,
                                                    unsigned long long b,
                                                    unsigned long long c) {
    unsigned long long d;
    asm("fma.rn.f32x2 %0, %1, %2, %3;" : "=l"(d) : "l"(a), "l"(b), "l"(c));
    return d;
}
__device__ __forceinline__ float tanhfast(float x) {
    float y;
    asm("tanh.approx.f32 %0, %1;" : "=f"(y) : "f"(x));
    return y;
}
__device__ __forceinline__ unsigned tanh_h2(unsigned x) {
    unsigned y;
    asm("tanh.approx.f16x2 %0, %1;" : "=r"(y) : "r"(x));
    return y;
}
__device__ __forceinline__ __half2 u2h(unsigned u) { return *(__half2*)&u; }
__device__ __forceinline__ unsigned h2u(__half2 h) { return *(unsigned*)&h; }

// ============================================================================
// Kernel A: projections -> half2. grid (18 n-tiles of 32, B, 2), 512 thr.
// Full-K staging, ONE barrier, batch-8 register prefetch in the FFMA2 loop.
// ============================================================================
#define PROJ_SMEM_BYTES ((256 * 32 + 256 * 66) * 4)

__global__ void __launch_bounds__(512) proj_kernel(
    const float* __restrict__ key, const float* __restrict__ query,
    const float* __restrict__ Wk,  const float* __restrict__ bk,
    const float* __restrict__ Wq,  const float* __restrict__ bq)
{
    extern __shared__ float smem[];
    float (*sX)[32] = (float (*)[32])smem;               // [256 ch][32 n]
    float (*sW)[66] = (float (*)[66])(smem + 256 * 32);  // [256 ch][64 c]

    const int kind = blockIdx.z;
    const float* X    = kind ? query : key;    // (B, CIN, N)
    const float* W    = kind ? Wq    : Wk;     // (CO, CIN)
    const float* bias = kind ? bq    : bk;
    unsigned* outp    = kind ? g_qph : g_kph;  // (B, N, 32) half2

    const int b  = blockIdx.y;
    const int n0 = blockIdx.x * 32;
    const int t  = threadIdx.x;

    {   // stage X: 256ch x 32n as float4 (coalesced)
        const int n4  = (t & 7) * 4;
        const int chb = t >> 3;                  // 0..63
        #pragma unroll
        for (int i = 0; i < 4; i++) {
            const int ch = chb + i * 64;
            *(float4*)&sX[ch][n4] =
                *(const float4*)&X[((size_t)(b * CIN + ch)) * N_ + n0 + n4];
        }
    }
    {   // stage W transposed: sW[ch][c]
        const int ch = t & 255;
        const int cb = (t >> 8) * 32;            // 0 or 32
        #pragma unroll 8
        for (int j = 0; j < 32; j++) {
            const int cr = cb + j;
            sW[ch][cr] = W[cr * CIN + ch];
        }
    }
    __syncthreads();

    const int ng = t & 15;           // n = 2*ng, 2*ng+1
    const int c  = (t >> 4) * 2;     // c, c+1

    unsigned long long a0 = 0ull, a1 = 0ull;

    for (int ch0 = 0; ch0 < CIN; ch0 += 8) {
        unsigned long long xps[8];
        float2 ws[8];
        #pragma unroll
        for (int i = 0; i < 8; i++) {
            xps[i] = *(const unsigned long long*)&sX[ch0 + i][ng * 2];
            ws[i]  = *(const float2*)&sW[ch0 + i][c];
        }
        #pragma unroll
        for (int i = 0; i < 8; i++) {
            a0 = ffma2(xps[i], pack2(ws[i].x, ws[i].x), a0);
            a1 = ffma2(xps[i], pack2(ws[i].y, ws[i].y), a1);
        }
    }

    const float bv0 = bias[c];
    const float bv1 = bias[c + 1];
    float c0n0, c0n1, c1n0, c1n1;
    unpack2(a0, c0n0, c0n1);
    unpack2(a1, c1n0, c1n1);

    const int n  = n0 + ng * 2;
    const int cc = c >> 1;
    outp[((size_t)b * N_ + n + 0) * 32 + cc] =
        h2u(__floats2half2_rn(c0n0 + bv0, c1n0 + bv1));
    outp[((size_t)b * N_ + n + 1) * 32 + cc] =
        h2u(__floats2half2_rn(c0n1 + bv0, c1n1 + bv1));
}

// ============================================================================
// Kernel B (FUSED v2): block = (16-q-tile, batch). Loops ALL 576 k in chunks
// of 32: attn chunk (f16x2 tanh) -> sA; FFMA2 contract with V chunk into
// per-thread accumulators; direct STG at the end. V + k-proj chunks are
// register-prefetched one chunk ahead into double-buffered smem.
// ============================================================================
// smem layout in 4B words
#define FS_SQH  0                         // uint [16][34]
#define FS_SWH  (FS_SQH + 16 * 34)        // uint [32]
#define FS_SKH  (FS_SWH + 32)             // uint [2][32][34]
#define FS_SA   (FS_SKH + 2 * 32 * 34)    // float[32][18]
#define FS_SV   (FS_SA + 32 * 18)         // float[2][32][260]
#define FUSED_SMEM_BYTES ((FS_SV + 2 * 32 * 260) * 4)

__global__ void __launch_bounds__(256) fused_kernel(
    const float* __restrict__ value, const float* __restrict__ wf,
    const float* __restrict__ bfp, float* __restrict__ out)
{
    extern __shared__ unsigned sm[];
    unsigned (*sqh)[34]      = (unsigned (*)[34])(sm + FS_SQH);
    unsigned* swh            = sm + FS_SWH;
    unsigned (*skh)[32][34]  = (unsigned (*)[32][34])(sm + FS_SKH);
    float (*sA)[18]          = (float (*)[18])(sm + FS_SA);
    float (*sV)[32][260]     = (float (*)[32][260])(sm + FS_SV);

    const int b  = blockIdx.y;
    const int q0 = blockIdx.x * 16;
    const int t  = threadIdx.x;

    // ---- stage q tile (16 x 32 uint) + wf ----
    if (t < 128) {
        const int r  = t >> 3;
        const int u4 = (t & 7) * 4;
        const uint4 v = *(const uint4*)&g_qph[((size_t)b * N_ + q0 + r) * 32 + u4];
        *(uint2*)&sqh[r][u4]     = make_uint2(v.x, v.y);
        *(uint2*)&sqh[r][u4 + 2] = make_uint2(v.z, v.w);
    } else if (t < 160) {
        const int i = t - 128;
        const float2 w = *(const float2*)&wf[i * 2];
        swh[i] = h2u(__floats2half2_rn(w.x, w.y));
    }
    // ---- stage chunk 0: k-proj + V ----
    {
        const int kk = t >> 3;
        const int u4 = (t & 7) * 4;
        const uint4 v = *(const uint4*)&g_kph[((size_t)b * N_ + kk) * 32 + u4];
        *(uint2*)&skh[0][kk][u4]     = make_uint2(v.x, v.y);
        *(uint2*)&skh[0][kk][u4 + 2] = make_uint2(v.z, v.w);
    }
    {
        const int kk = t & 31;
        const int cg = t >> 5;                 // 0..7
        const float* vp = value + ((size_t)(b * CV_ + cg)) * N_ + kk;
        #pragma unroll 8
        for (int j = 0; j < 32; j++)
            sV[0][kk][cg + 8 * j] = vp[(size_t)(8 * j) * N_];
    }
    const float bf = __ldg(bfp);
    __syncthreads();

    // attn mapping: k = lane-ish, two q per thread (qa, qa+8)
    const int ka = t & 31;
    const int qa = t >> 5;                     // 0..7
    const unsigned* __restrict__ qrowA = sqh[qa];
    const unsigned* __restrict__ qrowB = sqh[qa + 8];

    // FMA mapping: thread = 8c x 2q, acc packed over c-pairs
    const int qp = (t & 7) * 2;                // q, q+1
    const int c0 = (t >> 3) * 8;               // c0..c0+7
    unsigned long long acc[4][2];
    #pragma unroll
    for (int j = 0; j < 4; j++) { acc[j][0] = 0ull; acc[j][1] = 0ull; }

    for (int ch = 0; ch < NCHUNK; ch++) {
        const int buf  = ch & 1;
        const int nbuf = buf ^ 1;
        const bool pf  = (ch + 1 < NCHUNK);
        const int k0n  = (ch + 1) * 32;

        // ---- prefetch next chunk into regs (latency hidden by attn) ----
        float vreg[32];
        uint4 kreg;
        if (pf) {
            const int kk = t & 31;
            const int cg = t >> 5;
            const float* vp = value + ((size_t)(b * CV_ + cg)) * N_ + k0n + kk;
            #pragma unroll 8
            for (int j = 0; j < 32; j++)
                vreg[j] = vp[(size_t)(8 * j) * N_];
            const int kk3 = t >> 3;
            const int u4  = (t & 7) * 4;
            kreg = *(const uint4*)&g_kph[((size_t)b * N_ + k0n + kk3) * 32 + u4];
        }

        // ---- attn: 32k x 16q chunk -> sA ----
        {
            __half2 aeA = __float2half2_rn(0.f), aoA = aeA;
            __half2 aeB = aeA, aoB = aeA;
            const unsigned* __restrict__ krow = skh[buf][ka];
            #pragma unroll 8
            for (int cc = 0; cc < 32; cc += 2) {
                const uint2 kv = *(const uint2*)&krow[cc];
                const uint2 wv = *(const uint2*)&swh[cc];
                const uint2 qA = *(const uint2*)&qrowA[cc];
                const uint2 qB = *(const uint2*)&qrowB[cc];
                const unsigned tA0 = tanh_h2(h2u(__hadd2(u2h(kv.x), u2h(qA.x))));
                const unsigned tA1 = tanh_h2(h2u(__hadd2(u2h(kv.y), u2h(qA.y))));
                const unsigned tB0 = tanh_h2(h2u(__hadd2(u2h(kv.x), u2h(qB.x))));
                const unsigned tB1 = tanh_h2(h2u(__hadd2(u2h(kv.y), u2h(qB.y))));
                aeA = __hfma2(u2h(tA0), u2h(wv.x), aeA);
                aoA = __hfma2(u2h(tA1), u2h(wv.y), aoA);
                aeB = __hfma2(u2h(tB0), u2h(wv.x), aeB);
                aoB = __hfma2(u2h(tB1), u2h(wv.y), aoB);
            }
            const float2 feA = __half22float2(aeA);
            const float2 foA = __half22float2(aoA);
            const float2 feB = __half22float2(aeB);
            const float2 foB = __half22float2(aoB);
            const float sAv = bf + ((feA.x + feA.y) + (foA.x + foA.y));
            const float sBv = bf + ((feB.x + feB.y) + (foB.x + foB.y));
            sA[ka][qa]     = fmaf(0.5f, tanhfast(0.5f * sAv), 0.5f);
            sA[ka][qa + 8] = fmaf(0.5f, tanhfast(0.5f * sBv), 0.5f);
        }

        // ---- commit prefetched chunk into the other buffers ----
        if (pf) {
            const int kk = t & 31;
            const int cg = t >> 5;
            #pragma unroll 8
            for (int j = 0; j < 32; j++)
                sV[nbuf][kk][cg + 8 * j] = vreg[j];
            const int kk3 = t >> 3;
            const int u4  = (t & 7) * 4;
            *(uint2*)&skh[nbuf][kk3][u4]     = make_uint2(kreg.x, kreg.y);
            *(uint2*)&skh[nbuf][kk3][u4 + 2] = make_uint2(kreg.z, kreg.w);
        }
        __syncthreads();   // sA + next buffers ready

        // ---- FFMA2 contract: acc[c-pair][qi] += V[c,kk] * A[kk,q] ----
        #pragma unroll 4
        for (int kk = 0; kk < 32; kk++) {
            const float2 a2 = *(const float2*)&sA[kk][qp];
            const unsigned long long aa0 = pack2(a2.x, a2.x);
            const unsigned long long aa1 = pack2(a2.y, a2.y);
            const float* vrow = &sV[buf][kk][c0];
            const ulonglong2 v01 = *(const ulonglong2*)(vrow);      // c0..c0+3
            const ulonglong2 v23 = *(const ulonglong2*)(vrow + 4);  // c0+4..c0+7
            acc[0][0] = ffma2(v01.x, aa0, acc[0][0]);
            acc[0][1] = ffma2(v01.x, aa1, acc[0][1]);
            acc[1][0] = ffma2(v01.y, aa0, acc[1][0]);
            acc[1][1] = ffma2(v01.y, aa1, acc[1][1]);
            acc[2][0] = ffma2(v23.x, aa0, acc[2][0]);
            acc[2][1] = ffma2(v23.x, aa1, acc[2][1]);
            acc[3][0] = ffma2(v23.y, aa0, acc[3][0]);
            acc[3][1] = ffma2(v23.y, aa1, acc[3][1]);
        }
        __syncthreads();   // protect sA/sV[buf] before next chunk reuses them
    }

    // ---- write outputs: (c0..c0+7) x (qp, qp+1), no atomics ----
    float* op = out + ((size_t)(b * CV_ + c0)) * N_ + q0 + qp;
    #pragma unroll
    for (int j = 0; j < 4; j++) {
        float l0, h0, l1, h1;
        unpack2(acc[j][0], l0, h0);   // q = qp : c0+2j, c0+2j+1
        unpack2(acc[j][1], l1, h1);   // q = qp+1
        *(float2*)&op[(size_t)(2 * j) * N_]     = make_float2(l0, l1);
        *(float2*)&op[(size_t)(2 * j + 1) * N_] = make_float2(h0, h1);
    }
}

// ============================================================================
extern "C" void kernel_launch(void* const* d_in, const int* in_sizes, int n_in,
                              void* d_out, int out_size)
{
    const float* key   = (const float*)d_in[0];
    const float* query = (const float*)d_in[1];
    const float* value = (const float*)d_in[2];
    const float* Wk    = (const float*)d_in[3];
    const float* bk    = (const float*)d_in[4];
    const float* Wq    = (const float*)d_in[5];
    const float* bq    = (const float*)d_in[6];
    const float* wf    = (const float*)d_in[7];
    const float* bf    = (const float*)d_in[8];
    float* out = (float*)d_out;

    static int attr_set = 0;
    if (!attr_set) {
        cudaFuncSetAttribute(proj_kernel,
                             cudaFuncAttributeMaxDynamicSharedMemorySize,
                             PROJ_SMEM_BYTES);
        cudaFuncSetAttribute(fused_kernel,
                             cudaFuncAttributeMaxDynamicSharedMemorySize,
                             FUSED_SMEM_BYTES);
        attr_set = 1;
    }

    proj_kernel<<<dim3(N_ / 32, B_, 2), 512, PROJ_SMEM_BYTES>>>(key, query, Wk, bk, Wq, bq);
    fused_kernel<<<dim3(N_ / 16, B_), 256, FUSED_SMEM_BYTES>>>(value, wf, bf, out);
}

// round 9
// speedup vs baseline: 1.3450x; 1.2766x over previous
#include <cuda_runtime.h>
#include <cuda_fp16.h>

#define B_     4
#define CIN    256
#define CO_    64
#define N_     576   // 24*24
#define CV_    256

// Scratch (device globals — no allocation allowed)
__device__ unsigned g_kph[B_ * N_ * 32];   // (B, Nk, 32) half2 pairs over c
__device__ unsigned g_qph[B_ * N_ * 32];   // (B, Nq, 32)
__device__ float    g_attn[B_ * N_ * N_];  // (B, Nk, Nq)

// ---------- packed helpers ----------
__device__ __forceinline__ unsigned long long pack2(float lo, float hi) {
    unsigned long long r;
    asm("mov.b64 %0, {%1, %2};" : "=l"(r) : "f"(lo), "f"(hi));
    return r;
}
__device__ __forceinline__ void unpack2(unsigned long long v, float& lo, float& hi) {
    asm("mov.b64 {%0, %1}, %2;" : "=f"(lo), "=f"(hi) : "l"(v));
}
__device__ __forceinline__ unsigned long long ffma2(unsigned long long a,
                                                    unsigned long long b,
                                                    unsigned long long c) {
    unsigned long long d;
    asm("fma.rn.f32x2 %0, %1, %2, %3;" : "=l"(d) : "l"(a), "l"(b), "l"(c));
    return d;
}
__device__ __forceinline__ float tanhfast(float x) {
    float y;
    asm("tanh.approx.f32 %0, %1;" : "=f"(y) : "f"(x));
    return y;
}
__device__ __forceinline__ unsigned tanh_h2(unsigned x) {
    unsigned y;
    asm("tanh.approx.f16x2 %0, %1;" : "=r"(y) : "r"(x));
    return y;
}
__device__ __forceinline__ __half2 u2h(unsigned u) { return *(__half2*)&u; }
__device__ __forceinline__ unsigned h2u(__half2 h) { return *(unsigned*)&h; }

// ============================================================================
// Kernel A: projections -> half2. grid (18 n-tiles of 32, B, 2), 512 thr.
// Full-K staging, ONE barrier, batch-8 register prefetch in the FFMA2 loop.
// ============================================================================
#define PROJ_SMEM_BYTES ((256 * 32 + 256 * 66) * 4)

__global__ void __launch_bounds__(512) proj_kernel(
    const float* __restrict__ key, const float* __restrict__ query,
    const float* __restrict__ Wk,  const float* __restrict__ bk,
    const float* __restrict__ Wq,  const float* __restrict__ bq)
{
    extern __shared__ float smem[];
    float (*sX)[32] = (float (*)[32])smem;               // [256 ch][32 n]
    float (*sW)[66] = (float (*)[66])(smem + 256 * 32);  // [256 ch][64 c]

    const int kind = blockIdx.z;
    const float* X    = kind ? query : key;    // (B, CIN, N)
    const float* W    = kind ? Wq    : Wk;     // (CO, CIN)
    const float* bias = kind ? bq    : bk;
    unsigned* outp    = kind ? g_qph : g_kph;  // (B, N, 32) half2

    const int b  = blockIdx.y;
    const int n0 = blockIdx.x * 32;
    const int t  = threadIdx.x;

    {   // stage X: 256ch x 32n as float4 (coalesced)
        const int n4  = (t & 7) * 4;
        const int chb = t >> 3;                  // 0..63
        #pragma unroll
        for (int i = 0; i < 4; i++) {
            const int ch = chb + i * 64;
            *(float4*)&sX[ch][n4] =
                *(const float4*)&X[((size_t)(b * CIN + ch)) * N_ + n0 + n4];
        }
    }
    {   // stage W transposed: sW[ch][c]
        const int ch = t & 255;
        const int cb = (t >> 8) * 32;            // 0 or 32
        #pragma unroll 8
        for (int j = 0; j < 32; j++) {
            const int cr = cb + j;
            sW[ch][cr] = W[cr * CIN + ch];
        }
    }
    __syncthreads();

    const int ng = t & 15;           // n = 2*ng, 2*ng+1
    const int c  = (t >> 4) * 2;     // c, c+1

    unsigned long long a0 = 0ull, a1 = 0ull;

    for (int ch0 = 0; ch0 < CIN; ch0 += 8) {
        unsigned long long xps[8];
        float2 ws[8];
        #pragma unroll
        for (int i = 0; i < 8; i++) {
            xps[i] = *(const unsigned long long*)&sX[ch0 + i][ng * 2];
            ws[i]  = *(const float2*)&sW[ch0 + i][c];
        }
        #pragma unroll
        for (int i = 0; i < 8; i++) {
            a0 = ffma2(xps[i], pack2(ws[i].x, ws[i].x), a0);
            a1 = ffma2(xps[i], pack2(ws[i].y, ws[i].y), a1);
        }
    }

    const float bv0 = bias[c];
    const float bv1 = bias[c + 1];
    float c0n0, c0n1, c1n0, c1n1;
    unpack2(a0, c0n0, c0n1);
    unpack2(a1, c1n0, c1n1);

    const int n  = n0 + ng * 2;
    const int cc = c >> 1;
    outp[((size_t)b * N_ + n + 0) * 32 + cc] =
        h2u(__floats2half2_rn(c0n0 + bv0, c1n0 + bv1));
    outp[((size_t)b * N_ + n + 1) * 32 + cc] =
        h2u(__floats2half2_rn(c0n1 + bv0, c1n1 + bv1));
}

// ============================================================================
// Kernel B: attn[b,k,q] = sigmoid( bf + sum_c tanh(kp[k,c]+qp[q,c])*wf[c] )
// grid (18 q-tiles, 18 k-tiles, B) = 1296 blocks (~8/SM, 2048 thr/SM), 256 thr.
// Thread = 4k x 1q (q = lane). Pure f16 hot loop (HADD2 + tanh.f16x2 + HFMA2).
// ============================================================================
__global__ void __launch_bounds__(256) attn_kernel(
    const float* __restrict__ wf, const float* __restrict__ bfp)
{
    const int b  = blockIdx.z;
    const int k0 = blockIdx.y * 32;
    const int q0 = blockIdx.x * 32;

    __shared__ unsigned skh[32][34];   // half2 pairs over c
    __shared__ unsigned sqh[32][34];
    __shared__ unsigned swh[32];

    const int t = threadIdx.x;
    #pragma unroll
    for (int j = 0; j < 2; j++) {
        const int idx = t + j * 256;       // 512 uint2 per tile side
        const int r = idx >> 4;            // 0..31
        const int u = (idx & 15) * 2;
        *(uint2*)&skh[r][u] =
            *(const uint2*)&g_kph[((size_t)b * N_ + k0 + r) * 32 + u];
        *(uint2*)&sqh[r][u] =
            *(const uint2*)&g_qph[((size_t)b * N_ + q0 + r) * 32 + u];
    }
    if (t < 32) {
        const float2 w = *(const float2*)&wf[t * 2];
        swh[t] = h2u(__floats2half2_rn(w.x, w.y));
    }
    __syncthreads();

    const int q  = t & 31;            // lane -> CF q loads, coalesced STG
    const int k4 = (t >> 5) * 4;      // 4 k's (warp-constant -> broadcast)

    __half2 ae[4], ao[4];
    #pragma unroll
    for (int i = 0; i < 4; i++) { ae[i] = __float2half2_rn(0.f); ao[i] = ae[i]; }

    const unsigned* __restrict__ qrow = sqh[q];

    #pragma unroll
    for (int cc = 0; cc < 32; cc += 2) {
        const uint2 qv = *(const uint2*)&qrow[cc];
        const uint2 wv = *(const uint2*)&swh[cc];
        #pragma unroll
        for (int i = 0; i < 4; i++) {
            const uint2 kv = *(const uint2*)&skh[k4 + i][cc];
            const unsigned t0 = tanh_h2(h2u(__hadd2(u2h(kv.x), u2h(qv.x))));
            const unsigned t1 = tanh_h2(h2u(__hadd2(u2h(kv.y), u2h(qv.y))));
            ae[i] = __hfma2(u2h(t0), u2h(wv.x), ae[i]);
            ao[i] = __hfma2(u2h(t1), u2h(wv.y), ao[i]);
        }
    }

    const float bf = __ldg(bfp);
    #pragma unroll
    for (int i = 0; i < 4; i++) {
        const float2 fe = __half22float2(ae[i]);
        const float2 fo = __half22float2(ao[i]);
        const float s = bf + ((fe.x + fe.y) + (fo.x + fo.y));
        g_attn[((size_t)b * N_ + k0 + k4 + i) * N_ + q0 + q] =
            fmaf(0.5f, tanhfast(0.5f * s), 0.5f);   // sigmoid
    }
}

// ============================================================================
// Kernel C: out[b,c,q] = sum_k value[b,c,k] * attn[b,k,q]
// OCCUPANCY-FIRST: 128 thr, tile 32c x 32q, grid (18 q, 8 c, 4 b) = 576 blocks
// (~4 blocks/SM, 16 warps/SM). Thread = 4c x 2q. Inner kk = 2 LDS + 2 movs +
// 4 FFMA2 (balanced at the 2-issue-per-FFMA2 point).
// ============================================================================
__global__ void __launch_bounds__(128) out_kernel(
    const float* __restrict__ value, float* __restrict__ out)
{
    const int b  = blockIdx.z;
    const int c0 = blockIdx.y * 32;
    const int q0 = blockIdx.x * 32;

    __shared__ __align__(16) float sV[32][36];   // [k][c], 144B rows (16B mult)
    __shared__ __align__(16) float sA[32][36];   // [k][q]

    const int t  = threadIdx.x;
    const int qp = (t & 15) * 2;    // q = qp, qp+1
    const int cg = t >> 4;          // 0..7 -> c = cg*4 .. +3

    unsigned long long acc00 = 0ull, acc01 = 0ull, acc10 = 0ull, acc11 = 0ull;

    for (int k0 = 0; k0 < N_; k0 += 32) {
        {   // stage V: 32c x 32k -> sV[k][c] (coalesced LDG over k)
            const int kk = t & 31;
            const int cb = t >> 5;             // 0..3
            #pragma unroll
            for (int j = 0; j < 8; j++) {
                const int c = cb + j * 4;
                sV[kk][c] = value[((size_t)(b * CV_ + c0 + c)) * N_ + k0 + kk];
            }
        }
        {   // stage A: 32k x 32q (coalesced LDG over q, CF STS)
            const int q  = t & 31;
            const int kb = t >> 5;             // 0..3
            #pragma unroll
            for (int j = 0; j < 8; j++) {
                const int kr = kb + j * 4;
                sA[kr][q] = g_attn[((size_t)b * N_ + k0 + kr) * N_ + q0 + q];
            }
        }
        __syncthreads();

        #pragma unroll 8
        for (int kk = 0; kk < 32; kk++) {
            const ulonglong2 vp = *(const ulonglong2*)&sV[kk][cg * 4]; // c-pairs
            const float2     a2 = *(const float2*)&sA[kk][qp];        // 2 q
            const unsigned long long aa0 = pack2(a2.x, a2.x);
            const unsigned long long aa1 = pack2(a2.y, a2.y);
            acc00 = ffma2(vp.x, aa0, acc00);   // (c0,c1) x q0
            acc01 = ffma2(vp.x, aa1, acc01);   // (c0,c1) x q1
            acc10 = ffma2(vp.y, aa0, acc10);   // (c2,c3) x q0
            acc11 = ffma2(vp.y, aa1, acc11);   // (c2,c3) x q1
        }
        __syncthreads();
    }

    // write 4c x 2q as 4 STG.64 (q-consecutive)
    float v00, v01, v10, v11, w00, w01, w10, w11;
    unpack2(acc00, v00, v01);   // q0: c+0, c+1
    unpack2(acc01, w00, w01);   // q1: c+0, c+1
    unpack2(acc10, v10, v11);   // q0: c+2, c+3
    unpack2(acc11, w10, w11);   // q1: c+2, c+3

    float* op = out + ((size_t)(b * CV_ + c0 + cg * 4)) * N_ + q0 + qp;
    *(float2*)(op + 0 * N_) = make_float2(v00, w00);
    *(float2*)(op + 1 * N_) = make_float2(v01, w01);
    *(float2*)(op + 2 * N_) = make_float2(v10, w10);
    *(float2*)(op + 3 * N_) = make_float2(v11, w11);
}

// ============================================================================
extern "C" void kernel_launch(void* const* d_in, const int* in_sizes, int n_in,
                              void* d_out, int out_size)
{
    const float* key   = (const float*)d_in[0];
    const float* query = (const float*)d_in[1];
    const float* value = (const float*)d_in[2];
    const float* Wk    = (const float*)d_in[3];
    const float* bk    = (const float*)d_in[4];
    const float* Wq    = (const float*)d_in[5];
    const float* bq    = (const float*)d_in[6];
    const float* wf    = (const float*)d_in[7];
    const float* bf    = (const float*)d_in[8];
    float* out = (float*)d_out;

    static int attr_set = 0;
    if (!attr_set) {
        cudaFuncSetAttribute(proj_kernel,
                             cudaFuncAttributeMaxDynamicSharedMemorySize,
                             PROJ_SMEM_BYTES);
        attr_set = 1;
    }

    proj_kernel<<<dim3(N_ / 32, B_, 2), 512, PROJ_SMEM_BYTES>>>(key, query, Wk, bk, Wq, bq);
    attn_kernel<<<dim3(N_ / 32, N_ / 32, B_), 256>>>(wf, bf);
    out_kernel<<<dim3(N_ / 32, CV_ / 32, B_), 128>>>(value, out);
}

// round 10
// speedup vs baseline: 1.5917x; 1.1835x over previous
#include <cuda_runtime.h>
#include <cuda_fp16.h>

#define B_     4
#define CIN    256
#define CO_    64
#define N_     576   // 24*24
#define CV_    256
#define KSPLIT 3
#define CHUNKS 6     // 6 chunks of 32 k per split (3*6*32 = 576)

// Scratch (device globals — no allocation allowed)
__device__ unsigned g_kph[B_ * N_ * 32];   // (B, Nk, 32) half2 pairs over c
__device__ unsigned g_qph[B_ * N_ * 32];   // (B, Nq, 32)

// ---------- packed helpers ----------
__device__ __forceinline__ unsigned long long pack2(float lo, float hi) {
    unsigned long long r;
    asm("mov.b64 %0, {%1, %2};" : "=l"(r) : "f"(lo), "f"(hi));
    return r;
}
__device__ __forceinline__ void unpack2(unsigned long long v, float& lo, float& hi) {
    asm("mov.b64 {%0, %1}, %2;" : "=f"(lo), "=f"(hi) : "l"(v));
}
__device__ __forceinline__ unsigned long long ffma2(unsigned long long a,
                                                    unsigned long long b,
                                                    unsigned long long c) {
    unsigned long long d;
    asm("fma.rn.f32x2 %0, %1, %2, %3;" : "=l"(d) : "l"(a), "l"(b), "l"(c));
    return d;
}
__device__ __forceinline__ float tanhfast(float x) {
    float y;
    asm("tanh.approx.f32 %0, %1;" : "=f"(y) : "f"(x));
    return y;
}
__device__ __forceinline__ unsigned tanh_h2(unsigned x) {
    unsigned y;
    asm("tanh.approx.f16x2 %0, %1;" : "=r"(y) : "r"(x));
    return y;
}
__device__ __forceinline__ __half2 u2h(unsigned u) { return *(__half2*)&u; }
__device__ __forceinline__ unsigned h2u(__half2 h) { return *(unsigned*)&h; }

// ============================================================================
// Kernel A: projections -> half2, PLUS zero-init of d_out (kind-0 blocks).
// grid (18 n-tiles of 32, B, 2), 512 thr, __launch_bounds__(512,1) so ptxas
// has the 128-reg budget to keep the batch-8 prefetch in registers.
// ============================================================================
#define PROJ_SMEM_BYTES ((256 * 32 + 256 * 66) * 4)

__global__ void __launch_bounds__(512, 1) proj_kernel(
    const float* __restrict__ key, const float* __restrict__ query,
    const float* __restrict__ Wk,  const float* __restrict__ bk,
    const float* __restrict__ Wq,  const float* __restrict__ bq,
    float4* __restrict__ out_zero)
{
    extern __shared__ float smem[];
    float (*sX)[32] = (float (*)[32])smem;               // [256 ch][32 n]
    float (*sW)[66] = (float (*)[66])(smem + 256 * 32);  // [256 ch][64 c]

    const int kind = blockIdx.z;
    const float* X    = kind ? query : key;    // (B, CIN, N)
    const float* W    = kind ? Wq    : Wk;     // (CO, CIN)
    const float* bias = kind ? bq    : bk;
    unsigned* outp    = kind ? g_qph : g_kph;  // (B, N, 32) half2

    const int b  = blockIdx.y;
    const int n0 = blockIdx.x * 32;
    const int t  = threadIdx.x;

    // ---- zero d_out (kind-0 blocks; 72 blocks x 512 thr x 4 float4) ----
    if (kind == 0) {
        const int idx = (b * 18 + blockIdx.x) * 512 + t;   // 0..36863
        #pragma unroll
        for (int i = 0; i < 4; i++)
            out_zero[i * 36864 + idx] = make_float4(0.f, 0.f, 0.f, 0.f);
    }

    {   // stage X: 256ch x 32n as float4 (coalesced)
        const int n4  = (t & 7) * 4;
        const int chb = t >> 3;                  // 0..63
        #pragma unroll
        for (int i = 0; i < 4; i++) {
            const int ch = chb + i * 64;
            *(float4*)&sX[ch][n4] =
                *(const float4*)&X[((size_t)(b * CIN + ch)) * N_ + n0 + n4];
        }
    }
    {   // stage W transposed: sW[ch][c]
        const int ch = t & 255;
        const int cb = (t >> 8) * 32;            // 0 or 32
        #pragma unroll 8
        for (int j = 0; j < 32; j++) {
            const int cr = cb + j;
            sW[ch][cr] = W[cr * CIN + ch];
        }
    }
    __syncthreads();

    const int ng = t & 15;           // n = 2*ng, 2*ng+1
    const int c  = (t >> 4) * 2;     // c, c+1

    unsigned long long a0 = 0ull, a1 = 0ull;

    for (int ch0 = 0; ch0 < CIN; ch0 += 8) {
        unsigned long long xps[8];
        float2 ws[8];
        #pragma unroll
        for (int i = 0; i < 8; i++) {
            xps[i] = *(const unsigned long long*)&sX[ch0 + i][ng * 2];
            ws[i]  = *(const float2*)&sW[ch0 + i][c];
        }
        #pragma unroll
        for (int i = 0; i < 8; i++) {
            a0 = ffma2(xps[i], pack2(ws[i].x, ws[i].x), a0);
            a1 = ffma2(xps[i], pack2(ws[i].y, ws[i].y), a1);
        }
    }

    const float bv0 = bias[c];
    const float bv1 = bias[c + 1];
    float c0n0, c0n1, c1n0, c1n1;
    unpack2(a0, c0n0, c0n1);
    unpack2(a1, c1n0, c1n1);

    const int n  = n0 + ng * 2;
    const int cc = c >> 1;
    outp[((size_t)b * N_ + n + 0) * 32 + cc] =
        h2u(__floats2half2_rn(c0n0 + bv0, c1n0 + bv1));
    outp[((size_t)b * N_ + n + 1) * 32 + cc] =
        h2u(__floats2half2_rn(c0n1 + bv0, c1n1 + bv1));
}

// ============================================================================
// Kernel B (FUSED v3, occupancy-first): block = (16 q, 192 k-range, b).
// grid (36, 3, 4) = 432 blocks, 256 thr, <=64 regs -> ~3 blocks/SM resident;
// phase overlap comes from MULTI-BLOCK residency, not intra-block pipelining.
// Per 32k-chunk: stage (skh,sV) | attn (f16x2 tanh) -> sA | FFMA2 contract.
// Epilogue: atomicAdd the k-partial (out pre-zeroed by proj).
// ============================================================================
__global__ void __launch_bounds__(256, 4) fused_kernel(
    const float* __restrict__ value, const float* __restrict__ wf,
    const float* __restrict__ bfp, float* __restrict__ out)
{
    __shared__ unsigned sqh[16][34];   // q tile, half2 pairs over c
    __shared__ unsigned swh[32];
    __shared__ unsigned skh[32][34];   // current k chunk
    __shared__ float    sA[32][18];    // attn chunk [k][q]
    __shared__ __align__(16) float sV[32][260];  // V chunk [k][c]

    const int b  = blockIdx.z;
    const int q0 = blockIdx.x * 16;
    const int kbase = blockIdx.y * (CHUNKS * 32);
    const int t  = threadIdx.x;

    // ---- stage q tile + wf (once) ----
    {
        const int r = t >> 4;              // 0..15
        const int u = (t & 15) * 2;
        *(uint2*)&sqh[r][u] =
            *(const uint2*)&g_qph[((size_t)b * N_ + q0 + r) * 32 + u];
    }
    if (t < 32) {
        const float2 w = *(const float2*)&wf[t * 2];
        swh[t] = h2u(__floats2half2_rn(w.x, w.y));
    }
    const float bf = __ldg(bfp);

    // attn mapping: (ka, qa) and (ka, qa+8)
    const int ka = t & 31;
    const int qa = t >> 5;                 // 0..7

    // FMA mapping: thread = 8c x 2q
    const int qp = (t & 7) * 2;            // q, q+1
    const int c0 = (t >> 3) * 8;           // 0..248 step 8
    unsigned long long acc[4][2];
    #pragma unroll
    for (int j = 0; j < 4; j++) { acc[j][0] = 0ull; acc[j][1] = 0ull; }

    for (int ch = 0; ch < CHUNKS; ch++) {
        const int k0 = kbase + ch * 32;
        __syncthreads();   // previous FMA done: skh/sV/sA reusable

        // ---- stage skh (32x32 uint) ----
        {
            const int kk = t >> 3;
            const int u4 = (t & 7) * 4;
            const uint4 v = *(const uint4*)&g_kph[((size_t)b * N_ + k0 + kk) * 32 + u4];
            *(uint2*)&skh[kk][u4]     = make_uint2(v.x, v.y);
            *(uint2*)&skh[kk][u4 + 2] = make_uint2(v.z, v.w);
        }
        // ---- stage sV (32k x 256c), coalesced LDG over k ----
        {
            const int kk = t & 31;
            const int cg = t >> 5;             // 0..7
            const float* vp = value + ((size_t)(b * CV_ + cg)) * N_ + k0 + kk;
            #pragma unroll 8
            for (int j = 0; j < 32; j++)
                sV[kk][cg + 8 * j] = vp[(size_t)(8 * j) * N_];
        }
        __syncthreads();

        // ---- attn: 2 scores per thread ----
        {
            __half2 aeA = __float2half2_rn(0.f), aoA = aeA;
            __half2 aeB = aeA, aoB = aeA;
            const unsigned* __restrict__ krow  = skh[ka];
            const unsigned* __restrict__ qrowA = sqh[qa];
            const unsigned* __restrict__ qrowB = sqh[qa + 8];
            #pragma unroll 8
            for (int cc = 0; cc < 32; cc += 2) {
                const uint2 kv = *(const uint2*)&krow[cc];
                const uint2 wv = *(const uint2*)&swh[cc];
                const uint2 qA = *(const uint2*)&qrowA[cc];
                const uint2 qB = *(const uint2*)&qrowB[cc];
                const unsigned tA0 = tanh_h2(h2u(__hadd2(u2h(kv.x), u2h(qA.x))));
                const unsigned tA1 = tanh_h2(h2u(__hadd2(u2h(kv.y), u2h(qA.y))));
                const unsigned tB0 = tanh_h2(h2u(__hadd2(u2h(kv.x), u2h(qB.x))));
                const unsigned tB1 = tanh_h2(h2u(__hadd2(u2h(kv.y), u2h(qB.y))));
                aeA = __hfma2(u2h(tA0), u2h(wv.x), aeA);
                aoA = __hfma2(u2h(tA1), u2h(wv.y), aoA);
                aeB = __hfma2(u2h(tB0), u2h(wv.x), aeB);
                aoB = __hfma2(u2h(tB1), u2h(wv.y), aoB);
            }
            const float2 feA = __half22float2(aeA);
            const float2 foA = __half22float2(aoA);
            const float2 feB = __half22float2(aeB);
            const float2 foB = __half22float2(aoB);
            const float sAv = bf + ((feA.x + feA.y) + (foA.x + foA.y));
            const float sBv = bf + ((feB.x + feB.y) + (foB.x + foB.y));
            sA[ka][qa]     = fmaf(0.5f, tanhfast(0.5f * sAv), 0.5f);
            sA[ka][qa + 8] = fmaf(0.5f, tanhfast(0.5f * sBv), 0.5f);
        }
        __syncthreads();

        // ---- FFMA2 contract ----
        #pragma unroll 4
        for (int kk = 0; kk < 32; kk++) {
            const float2 a2 = *(const float2*)&sA[kk][qp];
            const unsigned long long aa0 = pack2(a2.x, a2.x);
            const unsigned long long aa1 = pack2(a2.y, a2.y);
            const float* vrow = &sV[kk][c0];
            const ulonglong2 v01 = *(const ulonglong2*)(vrow);      // c0..c0+3
            const ulonglong2 v23 = *(const ulonglong2*)(vrow + 4);  // c0+4..c0+7
            acc[0][0] = ffma2(v01.x, aa0, acc[0][0]);
            acc[0][1] = ffma2(v01.x, aa1, acc[0][1]);
            acc[1][0] = ffma2(v01.y, aa0, acc[1][0]);
            acc[1][1] = ffma2(v01.y, aa1, acc[1][1]);
            acc[2][0] = ffma2(v23.x, aa0, acc[2][0]);
            acc[2][1] = ffma2(v23.x, aa1, acc[2][1]);
            acc[3][0] = ffma2(v23.y, aa0, acc[3][0]);
            acc[3][1] = ffma2(v23.y, aa1, acc[3][1]);
        }
    }

    // ---- epilogue: atomicAdd k-partial (out zeroed by proj_kernel) ----
    #pragma unroll
    for (int j = 0; j < 4; j++) {
        float l0, h0, l1, h1;
        unpack2(acc[j][0], l0, h0);   // q=qp:   c0+2j, c0+2j+1
        unpack2(acc[j][1], l1, h1);   // q=qp+1: c0+2j, c0+2j+1
        float* op0 = out + ((size_t)(b * CV_ + c0 + 2 * j)) * N_ + q0 + qp;
        float* op1 = op0 + N_;
        atomicAdd(op0 + 0, l0);
        atomicAdd(op0 + 1, l1);
        atomicAdd(op1 + 0, h0);
        atomicAdd(op1 + 1, h1);
    }
}

// ============================================================================
extern "C" void kernel_launch(void* const* d_in, const int* in_sizes, int n_in,
                              void* d_out, int out_size)
{
    const float* key   = (const float*)d_in[0];
    const float* query = (const float*)d_in[1];
    const float* value = (const float*)d_in[2];
    const float* Wk    = (const float*)d_in[3];
    const float* bk    = (const float*)d_in[4];
    const float* Wq    = (const float*)d_in[5];
    const float* bq    = (const float*)d_in[6];
    const float* wf    = (const float*)d_in[7];
    const float* bf    = (const float*)d_in[8];
    float* out = (float*)d_out;

    static int attr_set = 0;
    if (!attr_set) {
        cudaFuncSetAttribute(proj_kernel,
                             cudaFuncAttributeMaxDynamicSharedMemorySize,
                             PROJ_SMEM_BYTES);
        attr_set = 1;
    }

    proj_kernel<<<dim3(N_ / 32, B_, 2), 512, PROJ_SMEM_BYTES>>>(
        key, query, Wk, bk, Wq, bq, (float4*)out);
    fused_kernel<<<dim3(N_ / 16, KSPLIT, B_), 256>>>(value, wf, bf, out);
}

// round 11
// speedup vs baseline: 1.7887x; 1.1237x over previous
#include <cuda_runtime.h>
#include <cuda_fp16.h>

#define B_     4
#define CIN    256
#define CO_    64
#define N_     576   // 24*24
#define CV_    256
#define KSPLIT 3
#define CHUNKS 6     // 6 chunks of 32 k per split (3*6*32 = 576)

// Scratch (device globals — no allocation allowed)
__device__ unsigned g_kph[B_ * N_ * 32];   // (B, Nk, 32) half2 pairs over c
__device__ unsigned g_qph[B_ * N_ * 32];   // (B, Nq, 32)

// ---------- packed helpers ----------
__device__ __forceinline__ unsigned long long pack2(float lo, float hi) {
    unsigned long long r;
    asm("mov.b64 %0, {%1, %2};" : "=l"(r) : "f"(lo), "f"(hi));
    return r;
}
__device__ __forceinline__ void unpack2(unsigned long long v, float& lo, float& hi) {
    asm("mov.b64 {%0, %1}, %2;" : "=f"(lo), "=f"(hi) : "l"(v));
}
__device__ __forceinline__ unsigned long long ffma2(unsigned long long a,
                                                    unsigned long long b,
                                                    unsigned long long c) {
    unsigned long long d;
    asm("fma.rn.f32x2 %0, %1, %2, %3;" : "=l"(d) : "l"(a), "l"(b), "l"(c));
    return d;
}
__device__ __forceinline__ float tanhfast(float x) {
    float y;
    asm("tanh.approx.f32 %0, %1;" : "=f"(y) : "f"(x));
    return y;
}
__device__ __forceinline__ unsigned tanh_h2(unsigned x) {
    unsigned y;
    asm("tanh.approx.f16x2 %0, %1;" : "=r"(y) : "r"(x));
    return y;
}
__device__ __forceinline__ __half2 u2h(unsigned u) { return *(__half2*)&u; }
__device__ __forceinline__ unsigned h2u(__half2 h) { return *(unsigned*)&h; }

// ============================================================================
// Kernel A: projections -> half2, PLUS zero-init of d_out (kind-0 blocks).
// grid (18 n-tiles of 32, B, 2), 512 thr, __launch_bounds__(512,1).
// ============================================================================
#define PROJ_SMEM_BYTES ((256 * 32 + 256 * 66) * 4)

__global__ void __launch_bounds__(512, 1) proj_kernel(
    const float* __restrict__ key, const float* __restrict__ query,
    const float* __restrict__ Wk,  const float* __restrict__ bk,
    const float* __restrict__ Wq,  const float* __restrict__ bq,
    float4* __restrict__ out_zero)
{
    extern __shared__ float smem[];
    float (*sX)[32] = (float (*)[32])smem;               // [256 ch][32 n]
    float (*sW)[66] = (float (*)[66])(smem + 256 * 32);  // [256 ch][64 c]

    const int kind = blockIdx.z;
    const float* X    = kind ? query : key;    // (B, CIN, N)
    const float* W    = kind ? Wq    : Wk;     // (CO, CIN)
    const float* bias = kind ? bq    : bk;
    unsigned* outp    = kind ? g_qph : g_kph;  // (B, N, 32) half2

    const int b  = blockIdx.y;
    const int n0 = blockIdx.x * 32;
    const int t  = threadIdx.x;

    // ---- zero d_out (kind-0 blocks; 72 blocks x 512 thr x 4 float4) ----
    if (kind == 0) {
        const int idx = (b * 18 + blockIdx.x) * 512 + t;   // 0..36863
        #pragma unroll
        for (int i = 0; i < 4; i++)
            out_zero[i * 36864 + idx] = make_float4(0.f, 0.f, 0.f, 0.f);
    }

    {   // stage X: 256ch x 32n as float4 (coalesced)
        const int n4  = (t & 7) * 4;
        const int chb = t >> 3;                  // 0..63
        #pragma unroll
        for (int i = 0; i < 4; i++) {
            const int ch = chb + i * 64;
            *(float4*)&sX[ch][n4] =
                *(const float4*)&X[((size_t)(b * CIN + ch)) * N_ + n0 + n4];
        }
    }
    {   // stage W transposed: sW[ch][c]
        const int ch = t & 255;
        const int cb = (t >> 8) * 32;            // 0 or 32
        #pragma unroll 8
        for (int j = 0; j < 32; j++) {
            const int cr = cb + j;
            sW[ch][cr] = W[cr * CIN + ch];
        }
    }
    __syncthreads();

    const int ng = t & 15;           // n = 2*ng, 2*ng+1
    const int c  = (t >> 4) * 2;     // c, c+1

    unsigned long long a0 = 0ull, a1 = 0ull;

    for (int ch0 = 0; ch0 < CIN; ch0 += 8) {
        unsigned long long xps[8];
        float2 ws[8];
        #pragma unroll
        for (int i = 0; i < 8; i++) {
            xps[i] = *(const unsigned long long*)&sX[ch0 + i][ng * 2];
            ws[i]  = *(const float2*)&sW[ch0 + i][c];
        }
        #pragma unroll
        for (int i = 0; i < 8; i++) {
            a0 = ffma2(xps[i], pack2(ws[i].x, ws[i].x), a0);
            a1 = ffma2(xps[i], pack2(ws[i].y, ws[i].y), a1);
        }
    }

    const float bv0 = bias[c];
    const float bv1 = bias[c + 1];
    float c0n0, c0n1, c1n0, c1n1;
    unpack2(a0, c0n0, c0n1);
    unpack2(a1, c1n0, c1n1);

    const int n  = n0 + ng * 2;
    const int cc = c >> 1;
    outp[((size_t)b * N_ + n + 0) * 32 + cc] =
        h2u(__floats2half2_rn(c0n0 + bv0, c1n0 + bv1));
    outp[((size_t)b * N_ + n + 1) * 32 + cc] =
        h2u(__floats2half2_rn(c0n1 + bv0, c1n1 + bv1));
}

// ============================================================================
// Kernel B (FUSED v4): as v3 but sV staging vectorized — 4 coalesced LDG.32
// packed into ONE STS.128 (bank16 = (kk+g) mod 8: perfect spread, 4-wf floor).
// Per-warp sV staging wavefronts: 160 -> 64. __launch_bounds__(256,3) gives
// ptxas ~84 regs so the 4-quad LDG batches stay in registers (MLP 16).
// ============================================================================
__global__ void __launch_bounds__(256, 3) fused_kernel(
    const float* __restrict__ value, const float* __restrict__ wf,
    const float* __restrict__ bfp, float* __restrict__ out)
{
    __shared__ unsigned sqh[16][34];   // q tile, half2 pairs over c
    __shared__ unsigned swh[32];
    __shared__ unsigned skh[32][34];   // current k chunk
    __shared__ float    sA[32][18];    // attn chunk [k][q]
    __shared__ __align__(16) float sV[32][260];  // [k][c], 1040B rows (16B mult)

    const int b  = blockIdx.z;
    const int q0 = blockIdx.x * 16;
    const int kbase = blockIdx.y * (CHUNKS * 32);
    const int t  = threadIdx.x;

    // ---- stage q tile + wf (once) ----
    {
        const int r = t >> 4;              // 0..15
        const int u = (t & 15) * 2;
        *(uint2*)&sqh[r][u] =
            *(const uint2*)&g_qph[((size_t)b * N_ + q0 + r) * 32 + u];
    }
    if (t < 32) {
        const float2 w = *(const float2*)&wf[t * 2];
        swh[t] = h2u(__floats2half2_rn(w.x, w.y));
    }
    const float bf = __ldg(bfp);

    // attn mapping: (ka, qa) and (ka, qa+8)
    const int ka = t & 31;
    const int qa = t >> 5;                 // 0..7

    // FMA mapping: thread = 8c x 2q
    const int qp = (t & 7) * 2;            // q, q+1
    const int c0 = (t >> 3) * 8;           // 0..248 step 8
    unsigned long long acc[4][2];
    #pragma unroll
    for (int j = 0; j < 4; j++) { acc[j][0] = 0ull; acc[j][1] = 0ull; }

    // staging mapping for sV: kk = lane, cq = quad base
    const int skk = t & 31;
    const int scq = (t >> 5) * 4;          // 0,4,..28

    for (int ch = 0; ch < CHUNKS; ch++) {
        const int k0 = kbase + ch * 32;
        __syncthreads();   // previous FMA done: skh/sV/sA reusable

        // ---- stage skh (32x32 uint) ----
        {
            const int kk = t >> 3;
            const int u4 = (t & 7) * 4;
            const uint4 v = *(const uint4*)&g_kph[((size_t)b * N_ + k0 + kk) * 32 + u4];
            *(uint2*)&skh[kk][u4]     = make_uint2(v.x, v.y);
            *(uint2*)&skh[kk][u4 + 2] = make_uint2(v.z, v.w);
        }
        // ---- stage sV: per thread 8 c-quads; each = 4 coalesced LDG.32
        //      packed into one STS.128 (two 4-quad batches, MLP 16) ----
        {
            const float* vb = value + ((size_t)b * CV_) * N_ + k0 + skk;
            #pragma unroll
            for (int half = 0; half < 2; half++) {
                float4 q[4];
                #pragma unroll
                for (int j = 0; j < 4; j++) {
                    const int cb2 = scq + (half * 4 + j) * 32;
                    q[j].x = vb[(size_t)(cb2 + 0) * N_];
                    q[j].y = vb[(size_t)(cb2 + 1) * N_];
                    q[j].z = vb[(size_t)(cb2 + 2) * N_];
                    q[j].w = vb[(size_t)(cb2 + 3) * N_];
                }
                #pragma unroll
                for (int j = 0; j < 4; j++) {
                    const int cb2 = scq + (half * 4 + j) * 32;
                    *(float4*)&sV[skk][cb2] = q[j];
                }
            }
        }
        __syncthreads();

        // ---- attn: 2 scores per thread ----
        {
            __half2 aeA = __float2half2_rn(0.f), aoA = aeA;
            __half2 aeB = aeA, aoB = aeA;
            const unsigned* __restrict__ krow  = skh[ka];
            const unsigned* __restrict__ qrowA = sqh[qa];
            const unsigned* __restrict__ qrowB = sqh[qa + 8];
            #pragma unroll 8
            for (int cc = 0; cc < 32; cc += 2) {
                const uint2 kv = *(const uint2*)&krow[cc];
                const uint2 wv = *(const uint2*)&swh[cc];
                const uint2 qA = *(const uint2*)&qrowA[cc];
                const uint2 qB = *(const uint2*)&qrowB[cc];
                const unsigned tA0 = tanh_h2(h2u(__hadd2(u2h(kv.x), u2h(qA.x))));
                const unsigned tA1 = tanh_h2(h2u(__hadd2(u2h(kv.y), u2h(qA.y))));
                const unsigned tB0 = tanh_h2(h2u(__hadd2(u2h(kv.x), u2h(qB.x))));
                const unsigned tB1 = tanh_h2(h2u(__hadd2(u2h(kv.y), u2h(qB.y))));
                aeA = __hfma2(u2h(tA0), u2h(wv.x), aeA);
                aoA = __hfma2(u2h(tA1), u2h(wv.y), aoA);
                aeB = __hfma2(u2h(tB0), u2h(wv.x), aeB);
                aoB = __hfma2(u2h(tB1), u2h(wv.y), aoB);
            }
            const float2 feA = __half22float2(aeA);
            const float2 foA = __half22float2(aoA);
            const float2 feB = __half22float2(aeB);
            const float2 foB = __half22float2(aoB);
            const float sAv = bf + ((feA.x + feA.y) + (foA.x + foA.y));
            const float sBv = bf + ((feB.x + feB.y) + (foB.x + foB.y));
            sA[ka][qa]     = fmaf(0.5f, tanhfast(0.5f * sAv), 0.5f);
            sA[ka][qa + 8] = fmaf(0.5f, tanhfast(0.5f * sBv), 0.5f);
        }
        __syncthreads();

        // ---- FFMA2 contract ----
        #pragma unroll 4
        for (int kk = 0; kk < 32; kk++) {
            const float2 a2 = *(const float2*)&sA[kk][qp];
            const unsigned long long aa0 = pack2(a2.x, a2.x);
            const unsigned long long aa1 = pack2(a2.y, a2.y);
            const float* vrow = &sV[kk][c0];
            const ulonglong2 v01 = *(const ulonglong2*)(vrow);      // c0..c0+3
            const ulonglong2 v23 = *(const ulonglong2*)(vrow + 4);  // c0+4..c0+7
            acc[0][0] = ffma2(v01.x, aa0, acc[0][0]);
            acc[0][1] = ffma2(v01.x, aa1, acc[0][1]);
            acc[1][0] = ffma2(v01.y, aa0, acc[1][0]);
            acc[1][1] = ffma2(v01.y, aa1, acc[1][1]);
            acc[2][0] = ffma2(v23.x, aa0, acc[2][0]);
            acc[2][1] = ffma2(v23.x, aa1, acc[2][1]);
            acc[3][0] = ffma2(v23.y, aa0, acc[3][0]);
            acc[3][1] = ffma2(v23.y, aa1, acc[3][1]);
        }
    }

    // ---- epilogue: atomicAdd k-partial (out zeroed by proj_kernel) ----
    #pragma unroll
    for (int j = 0; j < 4; j++) {
        float l0, h0, l1, h1;
        unpack2(acc[j][0], l0, h0);   // q=qp:   c0+2j, c0+2j+1
        unpack2(acc[j][1], l1, h1);   // q=qp+1: c0+2j, c0+2j+1
        float* op0 = out + ((size_t)(b * CV_ + c0 + 2 * j)) * N_ + q0 + qp;
        float* op1 = op0 + N_;
        atomicAdd(op0 + 0, l0);
        atomicAdd(op0 + 1, l1);
        atomicAdd(op1 + 0, h0);
        atomicAdd(op1 + 1, h1);
    }
}

// ============================================================================
extern "C" void kernel_launch(void* const* d_in, const int* in_sizes, int n_in,
                              void* d_out, int out_size)
{
    const float* key   = (const float*)d_in[0];
    const float* query = (const float*)d_in[1];
    const float* value = (const float*)d_in[2];
    const float* Wk    = (const float*)d_in[3];
    const float* bk    = (const float*)d_in[4];
    const float* Wq    = (const float*)d_in[5];
    const float* bq    = (const float*)d_in[6];
    const float* wf    = (const float*)d_in[7];
    const float* bf    = (const float*)d_in[8];
    float* out = (float*)d_out;

    static int attr_set = 0;
    if (!attr_set) {
        cudaFuncSetAttribute(proj_kernel,
                             cudaFuncAttributeMaxDynamicSharedMemorySize,
                             PROJ_SMEM_BYTES);
        attr_set = 1;
    }

    proj_kernel<<<dim3(N_ / 32, B_, 2), 512, PROJ_SMEM_BYTES>>>(
        key, query, Wk, bk, Wq, bq, (float4*)out);
    fused_kernel<<<dim3(N_ / 16, KSPLIT, B_), 256>>>(value, wf, bf, out);
}